// round 6
// baseline (speedup 1.0000x reference)
#include <cuda_runtime.h>

// Problem constants
#define BT   14          // batch rows per CTA
#define Hh   256         // hidden
#define Gg   1024        // 4*H gates
#define Tt   50          // encoder steps
#define Kk   3           // modes
#define FSn  6           // forecast steps
#define Bb   4096        // batch
#define NTH  1024        // threads per CTA (one per gate row)
#define NBLK ((Bb + BT - 1) / BT)   // 293

struct Smem {
  float h0[BT*Hh]; float c0[BT*Hh]; float h1[BT*Hh]; float c1[BT*Hh];   // working states
  float eh0[BT*Hh]; float ec0[BT*Hh]; float eh1[BT*Hh]; float ec1[BT*Hh]; // encoder-final snapshot
  float g[BT*Gg];          // gate pre-activations for current layer/step
  float xs[BT*Tt*4];       // staged input sequence for this CTA's rows
  float inp[BT*2];         // decoder feedback input
  float logit[BT*Kk];      // confidence logits
};

// ---- packed f32x2 helpers (Blackwell dual-rate fp32 path) ----
static __device__ __forceinline__ void f2fma(unsigned long long& d,
                                             unsigned long long a,
                                             unsigned long long b) {
  asm("fma.rn.f32x2 %0, %1, %2, %0;" : "+l"(d) : "l"(a), "l"(b));
}
static __device__ __forceinline__ unsigned long long f2z(float lo) {
  unsigned long long r;
  asm("mov.b64 %0, {%1, %2};" : "=l"(r) : "f"(lo), "f"(0.0f));
  return r;
}
static __device__ __forceinline__ float f2red(unsigned long long a) {
  float lo, hi;
  asm("mov.b64 {%0, %1}, %2;" : "=f"(lo), "=f"(hi) : "l"(a));
  return lo + hi;
}

// acc[b] (f32x2 pairs over K) += W[j, k..k+1..]*h[b, k..]  for all 14 rows.
// 1 LDG.128 per 4 K values, 14 LDS.128 (broadcast), 28 FFMA2.
static __device__ __forceinline__ void matvec_acc(
    const float* __restrict__ Wrow, const float* __restrict__ hs,
    unsigned long long* __restrict__ acc)
{
  ulonglong2 wv = *reinterpret_cast<const ulonglong2*>(Wrow);
  #pragma unroll 1
  for (int k = 0; k < Hh; k += 4) {
    ulonglong2 wc = wv;
    if (k + 4 < Hh) wv = *reinterpret_cast<const ulonglong2*>(Wrow + k + 4);
    #pragma unroll
    for (int b = 0; b < BT; b++) {
      ulonglong2 hv = *reinterpret_cast<const ulonglong2*>(hs + b*Hh + k);
      f2fma(acc[b], hv.x, wc.x);
      f2fma(acc[b], hv.y, wc.y);
    }
  }
}

static __device__ __forceinline__ float sigm(float x) {
  return 1.0f / (1.0f + __expf(-x));
}
static __device__ __forceinline__ float tanhx(float x) {
  x = fminf(15.0f, fmaxf(-15.0f, x));
  float e = __expf(2.0f * x);
  return (e - 1.0f) / (e + 1.0f);
}

// LSTM cell elementwise update: reads g (i|f|g|o layout), updates h,c in smem.
static __device__ __forceinline__ void cell_update(const float* __restrict__ g,
                                                   float* __restrict__ hs,
                                                   float* __restrict__ cs,
                                                   int tid) {
  for (int idx = tid; idx < BT*Hh; idx += NTH) {
    int b = idx >> 8;
    int u = idx & 255;
    const float* gb = g + b*Gg;
    float i_ = sigm(gb[u]);
    float f_ = sigm(gb[256 + u]);
    float tg = tanhx(gb[512 + u]);
    float o_ = sigm(gb[768 + u]);
    float c = f_ * cs[idx] + i_ * tg;
    cs[idx] = c;
    hs[idx] = o_ * tanhx(c);
  }
}

__global__ void __launch_bounds__(NTH, 1)
mml_kernel(const float* __restrict__ x,
           const float* __restrict__ eWih0, const float* __restrict__ eWhh0,
           const float* __restrict__ ebih0, const float* __restrict__ ebhh0,
           const float* __restrict__ eWih1, const float* __restrict__ eWhh1,
           const float* __restrict__ ebih1, const float* __restrict__ ebhh1,
           const float* __restrict__ dWih0, const float* __restrict__ dWhh0,
           const float* __restrict__ dbih0, const float* __restrict__ dbhh0,
           const float* __restrict__ dWih1, const float* __restrict__ dWhh1,
           const float* __restrict__ dbih1, const float* __restrict__ dbhh1,
           const float* __restrict__ headW, const float* __restrict__ headB,
           const float* __restrict__ confW, const float* __restrict__ confB,
           float* __restrict__ out)
{
  extern __shared__ char raw[];
  Smem* s = reinterpret_cast<Smem*>(raw);
  const int tid = threadIdx.x;
  const int j = tid;                       // gate row owned by this thread
  const int row0 = blockIdx.x * BT;

  // ---- init: zero states, stage x for our rows (clamped for padded rows) ----
  for (int idx = tid; idx < BT*Hh; idx += NTH) {
    s->h0[idx] = 0.f; s->c0[idx] = 0.f; s->h1[idx] = 0.f; s->c1[idx] = 0.f;
  }
  for (int idx = tid; idx < BT*Tt*4; idx += NTH) {
    int r = idx / (Tt*4);
    int off = idx - r*(Tt*4);
    int gr = min(row0 + r, Bb - 1);
    s->xs[idx] = x[gr*(Tt*4) + off];
  }
  __syncthreads();

  // per-thread persistent encoder constants
  const float b00 = ebih0[j] + ebhh0[j];
  const float b01 = ebih1[j] + ebhh1[j];
  const float4 wx0 = *reinterpret_cast<const float4*>(eWih0 + j*4);

  // ================= ENCODER =================
  for (int t = 0; t < Tt; t++) {
    // layer 0 gates
    {
      unsigned long long acc[BT];
      #pragma unroll
      for (int b = 0; b < BT; b++) {
        const float* xp = s->xs + b*Tt*4 + t*4;
        float init = b00 + wx0.x*xp[0] + wx0.y*xp[1] + wx0.z*xp[2] + wx0.w*xp[3];
        acc[b] = f2z(init);
      }
      matvec_acc(eWhh0 + j*Hh, s->h0, acc);
      #pragma unroll
      for (int b = 0; b < BT; b++) s->g[b*Gg + j] = f2red(acc[b]);
    }
    __syncthreads();
    cell_update(s->g, s->h0, s->c0, tid);
    __syncthreads();
    // layer 1 gates (two 256-matvecs: Wih1*h0 + Whh1*h1)
    {
      unsigned long long acc[BT];
      #pragma unroll
      for (int b = 0; b < BT; b++) acc[b] = f2z(b01);
      matvec_acc(eWih1 + j*Hh, s->h0, acc);
      matvec_acc(eWhh1 + j*Hh, s->h1, acc);
      #pragma unroll
      for (int b = 0; b < BT; b++) s->g[b*Gg + j] = f2red(acc[b]);
    }
    __syncthreads();
    cell_update(s->g, s->h1, s->c1, tid);
    __syncthreads();
  }

  // ---- snapshot encoder-final states ----
  for (int idx = tid; idx < BT*Hh; idx += NTH) {
    s->eh0[idx] = s->h0[idx]; s->ec0[idx] = s->c0[idx];
    s->eh1[idx] = s->h1[idx]; s->ec1[idx] = s->c1[idx];
  }
  __syncthreads();

  // ---- confidence head: logits = h1 @ conf_W.T + conf_b, softmax over K ----
  {
    int warp = tid >> 5, lane = tid & 31;
    for (int task = warp; task < BT*Kk; task += 32) {
      int b = task / Kk, k = task - b*Kk;
      float p = 0.f;
      for (int u = lane; u < Hh; u += 32)
        p += s->eh1[b*Hh + u] * confW[k*Hh + u];
      #pragma unroll
      for (int off = 16; off; off >>= 1) p += __shfl_down_sync(0xffffffffu, p, off);
      if (lane == 0) s->logit[b*Kk + k] = p + confB[k];
    }
  }
  __syncthreads();
  if (tid < BT) {
    int r = row0 + tid;
    float l0 = s->logit[tid*Kk + 0];
    float l1 = s->logit[tid*Kk + 1];
    float l2 = s->logit[tid*Kk + 2];
    float m = fmaxf(l0, fmaxf(l1, l2));
    float e0 = __expf(l0 - m), e1 = __expf(l1 - m), e2 = __expf(l2 - m);
    float inv = 1.f / (e0 + e1 + e2);
    if (r < Bb) {
      float* cp = out + (size_t)Bb*Kk*FSn*2 + (size_t)r*Kk;
      cp[0] = e0*inv; cp[1] = e1*inv; cp[2] = e2*inv;
    }
  }

  // ================= DECODER: K modes × FS steps =================
  for (int km = 0; km < Kk; km++) {
    __syncthreads();
    // restore encoder-final states; init feedback input = x[:, -1, :2]
    for (int idx = tid; idx < BT*Hh; idx += NTH) {
      s->h0[idx] = s->eh0[idx]; s->c0[idx] = s->ec0[idx];
      s->h1[idx] = s->eh1[idx]; s->c1[idx] = s->ec1[idx];
    }
    if (tid < BT*2) {
      int b = tid >> 1, d = tid & 1;
      s->inp[tid] = s->xs[b*Tt*4 + (Tt-1)*4 + d];
    }
    __syncthreads();

    const float db00 = dbih0[km*Gg + j] + dbhh0[km*Gg + j];
    const float db01 = dbih1[km*Gg + j] + dbhh1[km*Gg + j];
    const float2 wxd = *reinterpret_cast<const float2*>(dWih0 + (size_t)(km*Gg + j)*2);

    for (int t = 0; t < FSn; t++) {
      // layer 0
      {
        unsigned long long acc[BT];
        #pragma unroll
        for (int b = 0; b < BT; b++)
          acc[b] = f2z(db00 + wxd.x * s->inp[b*2 + 0] + wxd.y * s->inp[b*2 + 1]);
        matvec_acc(dWhh0 + (size_t)(km*Gg + j)*Hh, s->h0, acc);
        #pragma unroll
        for (int b = 0; b < BT; b++) s->g[b*Gg + j] = f2red(acc[b]);
      }
      __syncthreads();
      cell_update(s->g, s->h0, s->c0, tid);
      __syncthreads();
      // layer 1
      {
        unsigned long long acc[BT];
        #pragma unroll
        for (int b = 0; b < BT; b++) acc[b] = f2z(db01);
        matvec_acc(dWih1 + (size_t)(km*Gg + j)*Hh, s->h0, acc);
        matvec_acc(dWhh1 + (size_t)(km*Gg + j)*Hh, s->h1, acc);
        #pragma unroll
        for (int b = 0; b < BT; b++) s->g[b*Gg + j] = f2red(acc[b]);
      }
      __syncthreads();
      cell_update(s->g, s->h1, s->c1, tid);
      __syncthreads();
      // head: pred[b][d] = h1[b] . head_W[km][d] + head_b[km][d]; feed back + emit
      {
        int warp = tid >> 5, lane = tid & 31;
        for (int task = warp; task < BT*2; task += 32) {
          int b = task >> 1, d = task & 1;
          float p = 0.f;
          const float* hw = headW + (size_t)(km*2 + d)*Hh;
          for (int u = lane; u < Hh; u += 32)
            p += s->h1[b*Hh + u] * hw[u];
          #pragma unroll
          for (int off = 16; off; off >>= 1) p += __shfl_down_sync(0xffffffffu, p, off);
          if (lane == 0) {
            p += headB[km*2 + d];
            s->inp[b*2 + d] = p;
            int r = row0 + b;
            if (r < Bb)
              out[((((size_t)r*Kk + km)*FSn + t)*2) + d] = p;
          }
        }
      }
      __syncthreads();
    }
  }
}

extern "C" void kernel_launch(void* const* d_in, const int* in_sizes, int n_in,
                              void* d_out, int out_size) {
  (void)in_sizes; (void)n_in; (void)out_size;
  const float* x     = (const float*)d_in[0];
  const float* eWih0 = (const float*)d_in[1];
  const float* eWhh0 = (const float*)d_in[2];
  const float* ebih0 = (const float*)d_in[3];
  const float* ebhh0 = (const float*)d_in[4];
  const float* eWih1 = (const float*)d_in[5];
  const float* eWhh1 = (const float*)d_in[6];
  const float* ebih1 = (const float*)d_in[7];
  const float* ebhh1 = (const float*)d_in[8];
  const float* dWih0 = (const float*)d_in[9];
  const float* dWhh0 = (const float*)d_in[10];
  const float* dbih0 = (const float*)d_in[11];
  const float* dbhh0 = (const float*)d_in[12];
  const float* dWih1 = (const float*)d_in[13];
  const float* dWhh1 = (const float*)d_in[14];
  const float* dbih1 = (const float*)d_in[15];
  const float* dbhh1 = (const float*)d_in[16];
  const float* headW = (const float*)d_in[17];
  const float* headB = (const float*)d_in[18];
  const float* confW = (const float*)d_in[19];
  const float* confB = (const float*)d_in[20];
  float* out = (float*)d_out;

  const int smem_bytes = (int)sizeof(Smem);
  cudaFuncSetAttribute(mml_kernel, cudaFuncAttributeMaxDynamicSharedMemorySize,
                       smem_bytes);

  mml_kernel<<<NBLK, NTH, smem_bytes>>>(
      x, eWih0, eWhh0, ebih0, ebhh0, eWih1, eWhh1, ebih1, ebhh1,
      dWih0, dWhh0, dbih0, dbhh0, dWih1, dWhh1, dbih1, dbhh1,
      headW, headB, confW, confB, out);
}

// round 9
// speedup vs baseline: 1.3748x; 1.3748x over previous
#include <cuda_runtime.h>

// Problem constants
#define BT    14          // batch rows per CTA
#define Hh    256         // hidden
#define Gg    1024        // 4*H gates
#define Tt    50          // encoder steps
#define Kk    3           // modes
#define FSn   6           // forecast steps
#define Bb    4096        // batch
#define NTH   512         // threads per CTA (each owns TWO gate rows: j, j+512)
#define NWARP (NTH/32)
#define NBLK  ((Bb + BT - 1) / BT)   // 293

struct Smem {
  float h0[BT*Hh]; float c0[BT*Hh]; float h1[BT*Hh]; float c1[BT*Hh];   // working states
  float eh0[BT*Hh]; float ec0[BT*Hh]; float eh1[BT*Hh]; float ec1[BT*Hh]; // encoder-final snapshot
  float g[BT*Gg];          // gate pre-activations for current layer/step
  float xs[BT*Tt*4];       // staged input sequence for this CTA's rows
  float inp[BT*2];         // decoder feedback input
  float logit[BT*Kk];      // confidence logits
};

// ---- packed f32x2 helpers ----
static __device__ __forceinline__ void f2fma(unsigned long long& d,
                                             unsigned long long a,
                                             unsigned long long b) {
  asm("fma.rn.f32x2 %0, %1, %2, %0;" : "+l"(d) : "l"(a), "l"(b));
}
static __device__ __forceinline__ unsigned long long f2z(float lo) {
  unsigned long long r;
  asm("mov.b64 %0, {%1, %2};" : "=l"(r) : "f"(lo), "f"(0.0f));
  return r;
}
static __device__ __forceinline__ float f2red(unsigned long long a) {
  float lo, hi;
  asm("mov.b64 {%0, %1}, %2;" : "=f"(lo), "=f"(hi) : "l"(a));
  return lo + hi;
}

// Dual-row matvec: acc0[b] += W0[k..]*h[b,k..], acc1[b] += W1[k..]*h[b,k..].
// Per 4-K chunk: 14 LDS.128 (broadcast) feed 56 FFMA2 + 2 LDG.128.
static __device__ __forceinline__ void matvec_acc2(
    const float* __restrict__ W0, const float* __restrict__ W1,
    const float* __restrict__ hs,
    unsigned long long* __restrict__ acc0,
    unsigned long long* __restrict__ acc1)
{
  ulonglong2 w0 = *reinterpret_cast<const ulonglong2*>(W0);
  ulonglong2 w1 = *reinterpret_cast<const ulonglong2*>(W1);
  #pragma unroll 1
  for (int k = 0; k < Hh; k += 4) {
    ulonglong2 c0 = w0, c1 = w1;
    if (k + 4 < Hh) {
      w0 = *reinterpret_cast<const ulonglong2*>(W0 + k + 4);
      w1 = *reinterpret_cast<const ulonglong2*>(W1 + k + 4);
    }
    #pragma unroll
    for (int b = 0; b < BT; b++) {
      ulonglong2 hv = *reinterpret_cast<const ulonglong2*>(hs + b*Hh + k);
      f2fma(acc0[b], hv.x, c0.x);
      f2fma(acc0[b], hv.y, c0.y);
      f2fma(acc1[b], hv.x, c1.x);
      f2fma(acc1[b], hv.y, c1.y);
    }
  }
}

static __device__ __forceinline__ float sigm(float x) {
  return 1.0f / (1.0f + __expf(-x));
}
static __device__ __forceinline__ float tanhx(float x) {
  x = fminf(15.0f, fmaxf(-15.0f, x));
  float e = __expf(2.0f * x);
  return (e - 1.0f) / (e + 1.0f);
}

// LSTM cell elementwise update: reads g (i|f|g|o layout), updates h,c in smem.
static __device__ __forceinline__ void cell_update(const float* __restrict__ g,
                                                   float* __restrict__ hs,
                                                   float* __restrict__ cs,
                                                   int tid) {
  #pragma unroll 1
  for (int idx = tid; idx < BT*Hh; idx += NTH) {
    int b = idx >> 8;
    int u = idx & 255;
    const float* gb = g + b*Gg;
    float i_ = sigm(gb[u]);
    float f_ = sigm(gb[256 + u]);
    float tg = tanhx(gb[512 + u]);
    float o_ = sigm(gb[768 + u]);
    float c = f_ * cs[idx] + i_ * tg;
    cs[idx] = c;
    hs[idx] = o_ * tanhx(c);
  }
}

__global__ void __launch_bounds__(NTH, 1)
mml_kernel(const float* __restrict__ x,
           const float* __restrict__ eWih0, const float* __restrict__ eWhh0,
           const float* __restrict__ ebih0, const float* __restrict__ ebhh0,
           const float* __restrict__ eWih1, const float* __restrict__ eWhh1,
           const float* __restrict__ ebih1, const float* __restrict__ ebhh1,
           const float* __restrict__ dWih0, const float* __restrict__ dWhh0,
           const float* __restrict__ dbih0, const float* __restrict__ dbhh0,
           const float* __restrict__ dWih1, const float* __restrict__ dWhh1,
           const float* __restrict__ dbih1, const float* __restrict__ dbhh1,
           const float* __restrict__ headW, const float* __restrict__ headB,
           const float* __restrict__ confW, const float* __restrict__ confB,
           float* __restrict__ out)
{
  extern __shared__ char raw[];
  Smem* s = reinterpret_cast<Smem*>(raw);
  const int tid = threadIdx.x;
  const int jA = tid;          // first gate row owned by this thread
  const int jB = tid + NTH;    // second gate row
  const int row0 = blockIdx.x * BT;

  // ---- init: zero states, stage x for our rows (clamped for padded rows) ----
  for (int idx = tid; idx < BT*Hh; idx += NTH) {
    s->h0[idx] = 0.f; s->c0[idx] = 0.f; s->h1[idx] = 0.f; s->c1[idx] = 0.f;
  }
  for (int idx = tid; idx < BT*Tt*4; idx += NTH) {
    int r = idx / (Tt*4);
    int off = idx - r*(Tt*4);
    int gr = min(row0 + r, Bb - 1);
    s->xs[idx] = x[gr*(Tt*4) + off];
  }
  __syncthreads();

  // per-thread persistent encoder constants (two rows)
  const float b00A = ebih0[jA] + ebhh0[jA];
  const float b00B = ebih0[jB] + ebhh0[jB];
  const float b01A = ebih1[jA] + ebhh1[jA];
  const float b01B = ebih1[jB] + ebhh1[jB];
  const float4 wx0A = *reinterpret_cast<const float4*>(eWih0 + jA*4);
  const float4 wx0B = *reinterpret_cast<const float4*>(eWih0 + jB*4);

  // ================= ENCODER =================
  for (int t = 0; t < Tt; t++) {
    // layer 0 gates
    {
      unsigned long long accA[BT], accB[BT];
      #pragma unroll
      for (int b = 0; b < BT; b++) {
        const float* xp = s->xs + b*Tt*4 + t*4;
        float x0 = xp[0], x1 = xp[1], x2 = xp[2], x3 = xp[3];
        accA[b] = f2z(b00A + wx0A.x*x0 + wx0A.y*x1 + wx0A.z*x2 + wx0A.w*x3);
        accB[b] = f2z(b00B + wx0B.x*x0 + wx0B.y*x1 + wx0B.z*x2 + wx0B.w*x3);
      }
      matvec_acc2(eWhh0 + (size_t)jA*Hh, eWhh0 + (size_t)jB*Hh, s->h0, accA, accB);
      #pragma unroll
      for (int b = 0; b < BT; b++) {
        s->g[b*Gg + jA] = f2red(accA[b]);
        s->g[b*Gg + jB] = f2red(accB[b]);
      }
    }
    __syncthreads();
    cell_update(s->g, s->h0, s->c0, tid);
    __syncthreads();
    // layer 1 gates (Wih1*h0 + Whh1*h1)
    {
      unsigned long long accA[BT], accB[BT];
      #pragma unroll
      for (int b = 0; b < BT; b++) { accA[b] = f2z(b01A); accB[b] = f2z(b01B); }
      matvec_acc2(eWih1 + (size_t)jA*Hh, eWih1 + (size_t)jB*Hh, s->h0, accA, accB);
      matvec_acc2(eWhh1 + (size_t)jA*Hh, eWhh1 + (size_t)jB*Hh, s->h1, accA, accB);
      #pragma unroll
      for (int b = 0; b < BT; b++) {
        s->g[b*Gg + jA] = f2red(accA[b]);
        s->g[b*Gg + jB] = f2red(accB[b]);
      }
    }
    __syncthreads();
    cell_update(s->g, s->h1, s->c1, tid);
    __syncthreads();
  }

  // ---- snapshot encoder-final states ----
  for (int idx = tid; idx < BT*Hh; idx += NTH) {
    s->eh0[idx] = s->h0[idx]; s->ec0[idx] = s->c0[idx];
    s->eh1[idx] = s->h1[idx]; s->ec1[idx] = s->c1[idx];
  }
  __syncthreads();

  // ---- confidence head: logits = h1 @ conf_W.T + conf_b, softmax over K ----
  {
    int warp = tid >> 5, lane = tid & 31;
    for (int task = warp; task < BT*Kk; task += NWARP) {
      int b = task / Kk, k = task - b*Kk;
      float p = 0.f;
      for (int u = lane; u < Hh; u += 32)
        p += s->eh1[b*Hh + u] * confW[k*Hh + u];
      #pragma unroll
      for (int off = 16; off; off >>= 1) p += __shfl_down_sync(0xffffffffu, p, off);
      if (lane == 0) s->logit[b*Kk + k] = p + confB[k];
    }
  }
  __syncthreads();
  if (tid < BT) {
    int r = row0 + tid;
    float l0 = s->logit[tid*Kk + 0];
    float l1 = s->logit[tid*Kk + 1];
    float l2 = s->logit[tid*Kk + 2];
    float m = fmaxf(l0, fmaxf(l1, l2));
    float e0 = __expf(l0 - m), e1 = __expf(l1 - m), e2 = __expf(l2 - m);
    float inv = 1.f / (e0 + e1 + e2);
    if (r < Bb) {
      float* cp = out + (size_t)Bb*Kk*FSn*2 + (size_t)r*Kk;
      cp[0] = e0*inv; cp[1] = e1*inv; cp[2] = e2*inv;
    }
  }

  // ================= DECODER: K modes × FS steps =================
  for (int km = 0; km < Kk; km++) {
    __syncthreads();
    // restore encoder-final states; init feedback input = x[:, -1, :2]
    for (int idx = tid; idx < BT*Hh; idx += NTH) {
      s->h0[idx] = s->eh0[idx]; s->c0[idx] = s->ec0[idx];
      s->h1[idx] = s->eh1[idx]; s->c1[idx] = s->ec1[idx];
    }
    if (tid < BT*2) {
      int b = tid >> 1, d = tid & 1;
      s->inp[tid] = s->xs[b*Tt*4 + (Tt-1)*4 + d];
    }
    __syncthreads();

    const float db00A = dbih0[km*Gg + jA] + dbhh0[km*Gg + jA];
    const float db00B = dbih0[km*Gg + jB] + dbhh0[km*Gg + jB];
    const float db01A = dbih1[km*Gg + jA] + dbhh1[km*Gg + jA];
    const float db01B = dbih1[km*Gg + jB] + dbhh1[km*Gg + jB];
    const float2 wxdA = *reinterpret_cast<const float2*>(dWih0 + (size_t)(km*Gg + jA)*2);
    const float2 wxdB = *reinterpret_cast<const float2*>(dWih0 + (size_t)(km*Gg + jB)*2);

    for (int t = 0; t < FSn; t++) {
      // layer 0
      {
        unsigned long long accA[BT], accB[BT];
        #pragma unroll
        for (int b = 0; b < BT; b++) {
          float i0 = s->inp[b*2 + 0], i1 = s->inp[b*2 + 1];
          accA[b] = f2z(db00A + wxdA.x*i0 + wxdA.y*i1);
          accB[b] = f2z(db00B + wxdB.x*i0 + wxdB.y*i1);
        }
        matvec_acc2(dWhh0 + (size_t)(km*Gg + jA)*Hh,
                    dWhh0 + (size_t)(km*Gg + jB)*Hh, s->h0, accA, accB);
        #pragma unroll
        for (int b = 0; b < BT; b++) {
          s->g[b*Gg + jA] = f2red(accA[b]);
          s->g[b*Gg + jB] = f2red(accB[b]);
        }
      }
      __syncthreads();
      cell_update(s->g, s->h0, s->c0, tid);
      __syncthreads();
      // layer 1
      {
        unsigned long long accA[BT], accB[BT];
        #pragma unroll
        for (int b = 0; b < BT; b++) { accA[b] = f2z(db01A); accB[b] = f2z(db01B); }
        matvec_acc2(dWih1 + (size_t)(km*Gg + jA)*Hh,
                    dWih1 + (size_t)(km*Gg + jB)*Hh, s->h0, accA, accB);
        matvec_acc2(dWhh1 + (size_t)(km*Gg + jA)*Hh,
                    dWhh1 + (size_t)(km*Gg + jB)*Hh, s->h1, accA, accB);
        #pragma unroll
        for (int b = 0; b < BT; b++) {
          s->g[b*Gg + jA] = f2red(accA[b]);
          s->g[b*Gg + jB] = f2red(accB[b]);
        }
      }
      __syncthreads();
      cell_update(s->g, s->h1, s->c1, tid);
      __syncthreads();
      // head: pred[b][d] = h1[b] . head_W[km][d] + head_b[km][d]; feed back + emit
      {
        int warp = tid >> 5, lane = tid & 31;
        for (int task = warp; task < BT*2; task += NWARP) {
          int b = task >> 1, d = task & 1;
          float p = 0.f;
          const float* hw = headW + (size_t)(km*2 + d)*Hh;
          for (int u = lane; u < Hh; u += 32)
            p += s->h1[b*Hh + u] * hw[u];
          #pragma unroll
          for (int off = 16; off; off >>= 1) p += __shfl_down_sync(0xffffffffu, p, off);
          if (lane == 0) {
            p += headB[km*2 + d];
            s->inp[b*2 + d] = p;
            int r = row0 + b;
            if (r < Bb)
              out[((((size_t)r*Kk + km)*FSn + t)*2) + d] = p;
          }
        }
      }
      __syncthreads();
    }
  }
}

extern "C" void kernel_launch(void* const* d_in, const int* in_sizes, int n_in,
                              void* d_out, int out_size) {
  (void)in_sizes; (void)n_in; (void)out_size;
  const float* x     = (const float*)d_in[0];
  const float* eWih0 = (const float*)d_in[1];
  const float* eWhh0 = (const float*)d_in[2];
  const float* ebih0 = (const float*)d_in[3];
  const float* ebhh0 = (const float*)d_in[4];
  const float* eWih1 = (const float*)d_in[5];
  const float* eWhh1 = (const float*)d_in[6];
  const float* ebih1 = (const float*)d_in[7];
  const float* ebhh1 = (const float*)d_in[8];
  const float* dWih0 = (const float*)d_in[9];
  const float* dWhh0 = (const float*)d_in[10];
  const float* dbih0 = (const float*)d_in[11];
  const float* dbhh0 = (const float*)d_in[12];
  const float* dWih1 = (const float*)d_in[13];
  const float* dWhh1 = (const float*)d_in[14];
  const float* dbih1 = (const float*)d_in[15];
  const float* dbhh1 = (const float*)d_in[16];
  const float* headW = (const float*)d_in[17];
  const float* headB = (const float*)d_in[18];
  const float* confW = (const float*)d_in[19];
  const float* confB = (const float*)d_in[20];
  float* out = (float*)d_out;

  const int smem_bytes = (int)sizeof(Smem);
  cudaFuncSetAttribute(mml_kernel, cudaFuncAttributeMaxDynamicSharedMemorySize,
                       smem_bytes);

  mml_kernel<<<NBLK, NTH, smem_bytes>>>(
      x, eWih0, eWhh0, ebih0, ebhh0, eWih1, eWhh1, ebih1, ebhh1,
      dWih0, dWhh0, dbih0, dbhh0, dWih1, dWhh1, dbih1, dbhh1,
      headW, headB, confW, confB, out);
}

// round 10
// speedup vs baseline: 1.5757x; 1.1461x over previous
#include <cuda_runtime.h>

// Problem constants
#define BT    14          // batch rows per CTA
#define Hh    256         // hidden
#define Gg    1024        // 4*H gates
#define Tt    50          // encoder steps
#define Kk    3           // modes
#define FSn   6           // forecast steps
#define Bb    4096        // batch
#define NTH   256         // threads: thread j owns gates (i,f,g,o) of hidden unit j
#define NWARP (NTH/32)
#define NBLK  ((Bb + BT - 1) / BT)   // 293

typedef unsigned long long ull;

struct Smem {
  float h0[2][BT*Hh];      // double-buffered layer-0 hidden
  float h1[2][BT*Hh];      // double-buffered layer-1 hidden
  float c0[BT*Hh];         // cell states (thread-private: only thread j touches [*,j])
  float c1[BT*Hh];
  float eh0[BT*Hh]; float ec0[BT*Hh];   // encoder-final snapshot
  float eh1[BT*Hh]; float ec1[BT*Hh];
  float xs[BT*Tt*4];       // staged input sequence
  float inp[BT*2];         // decoder feedback input
  float logit[BT*Kk];      // confidence logits
};

// ---- packed f32x2 helpers ----
static __device__ __forceinline__ void f2fma(ull& d, ull a, ull b) {
  asm("fma.rn.f32x2 %0, %1, %2, %0;" : "+l"(d) : "l"(a), "l"(b));
}
static __device__ __forceinline__ ull f2z(float lo) {
  ull r;
  asm("mov.b64 %0, {%1, %2};" : "=l"(r) : "f"(lo), "f"(0.0f));
  return r;
}
static __device__ __forceinline__ float f2red(ull a) {
  float lo, hi;
  asm("mov.b64 {%0, %1}, %2;" : "=f"(lo), "=f"(hi) : "l"(a));
  return lo + hi;
}

static __device__ __forceinline__ float sigm(float x) {
  return 1.0f / (1.0f + __expf(-x));
}
static __device__ __forceinline__ float tanhx(float x) {
  x = fminf(15.0f, fmaxf(-15.0f, x));
  float e = __expf(2.0f * x);
  return (e - 1.0f) / (e + 1.0f);
}

// Quad-row matvec: for gate rows j, j+256, j+512, j+768 of W [1024x256],
// acc{I,F,G,O}[b] += W[row, k..]*h[b, k..] over all 14 batch rows.
// Per 4-K chunk: 14 broadcast LDS.128 feed 112 FFMA2 (+4 LDG.128).
static __device__ __forceinline__ void matvec4(
    const float* __restrict__ Wbase, int j,
    const float* __restrict__ hs,
    ull* __restrict__ accI, ull* __restrict__ accF,
    ull* __restrict__ accG, ull* __restrict__ accO)
{
  const float* Wi = Wbase + (size_t)j * Hh;
  const float* Wf = Wbase + (size_t)(j + 256) * Hh;
  const float* Wg = Wbase + (size_t)(j + 512) * Hh;
  const float* Wo = Wbase + (size_t)(j + 768) * Hh;
  ulonglong2 wi = *reinterpret_cast<const ulonglong2*>(Wi);
  ulonglong2 wf = *reinterpret_cast<const ulonglong2*>(Wf);
  ulonglong2 wg = *reinterpret_cast<const ulonglong2*>(Wg);
  ulonglong2 wo = *reinterpret_cast<const ulonglong2*>(Wo);
  #pragma unroll 1
  for (int k = 0; k < Hh; k += 4) {
    ulonglong2 ci = wi, cf = wf, cg = wg, co = wo;
    if (k + 4 < Hh) {
      wi = *reinterpret_cast<const ulonglong2*>(Wi + k + 4);
      wf = *reinterpret_cast<const ulonglong2*>(Wf + k + 4);
      wg = *reinterpret_cast<const ulonglong2*>(Wg + k + 4);
      wo = *reinterpret_cast<const ulonglong2*>(Wo + k + 4);
    }
    #pragma unroll
    for (int b = 0; b < BT; b++) {
      ulonglong2 hv = *reinterpret_cast<const ulonglong2*>(hs + b*Hh + k);
      f2fma(accI[b], hv.x, ci.x); f2fma(accI[b], hv.y, ci.y);
      f2fma(accF[b], hv.x, cf.x); f2fma(accF[b], hv.y, cf.y);
      f2fma(accG[b], hv.x, cg.x); f2fma(accG[b], hv.y, cg.y);
      f2fma(accO[b], hv.x, co.x); f2fma(accO[b], hv.y, co.y);
    }
  }
}

// In-register cell epilogue: fold accumulators, apply gates, update private c
// in smem, write new h into hnew[b*Hh + j].
static __device__ __forceinline__ void cell_epilogue(
    const ull* __restrict__ accI, const ull* __restrict__ accF,
    const ull* __restrict__ accG, const ull* __restrict__ accO,
    float* __restrict__ cs, float* __restrict__ hnew, int j)
{
  #pragma unroll
  for (int b = 0; b < BT; b++) {
    float gi = f2red(accI[b]);
    float gf = f2red(accF[b]);
    float gg = f2red(accG[b]);
    float go = f2red(accO[b]);
    float i_ = sigm(gi);
    float f_ = sigm(gf);
    float g_ = tanhx(gg);
    float o_ = sigm(go);
    float c  = f_ * cs[b*Hh + j] + i_ * g_;
    cs[b*Hh + j]   = c;
    hnew[b*Hh + j] = o_ * tanhx(c);
  }
}

__global__ void __launch_bounds__(NTH, 1)
mml_kernel(const float* __restrict__ x,
           const float* __restrict__ eWih0, const float* __restrict__ eWhh0,
           const float* __restrict__ ebih0, const float* __restrict__ ebhh0,
           const float* __restrict__ eWih1, const float* __restrict__ eWhh1,
           const float* __restrict__ ebih1, const float* __restrict__ ebhh1,
           const float* __restrict__ dWih0, const float* __restrict__ dWhh0,
           const float* __restrict__ dbih0, const float* __restrict__ dbhh0,
           const float* __restrict__ dWih1, const float* __restrict__ dWhh1,
           const float* __restrict__ dbih1, const float* __restrict__ dbhh1,
           const float* __restrict__ headW, const float* __restrict__ headB,
           const float* __restrict__ confW, const float* __restrict__ confB,
           float* __restrict__ out)
{
  extern __shared__ char raw[];
  Smem* s = reinterpret_cast<Smem*>(raw);
  const int tid = threadIdx.x;
  const int j = tid;                 // hidden unit owned by this thread
  const int row0 = blockIdx.x * BT;

  // ---- init: zero states, stage x for our rows (clamped for padded rows) ----
  for (int idx = tid; idx < BT*Hh; idx += NTH) {
    s->h0[0][idx] = 0.f; s->h1[0][idx] = 0.f;
    s->c0[idx] = 0.f;    s->c1[idx] = 0.f;
  }
  for (int idx = tid; idx < BT*Tt*4; idx += NTH) {
    int r = idx / (Tt*4);
    int off = idx - r*(Tt*4);
    int gr = min(row0 + r, Bb - 1);
    s->xs[idx] = x[gr*(Tt*4) + off];
  }
  __syncthreads();

  // ================= ENCODER =================
  {
    // per-thread constants for the 4 gate rows of unit j
    const float bi0 = ebih0[j]       + ebhh0[j];
    const float bf0 = ebih0[256 + j] + ebhh0[256 + j];
    const float bg0 = ebih0[512 + j] + ebhh0[512 + j];
    const float bo0 = ebih0[768 + j] + ebhh0[768 + j];
    const float bi1 = ebih1[j]       + ebhh1[j];
    const float bf1 = ebih1[256 + j] + ebhh1[256 + j];
    const float bg1 = ebih1[512 + j] + ebhh1[512 + j];
    const float bo1 = ebih1[768 + j] + ebhh1[768 + j];

    int p = 0;
    for (int t = 0; t < Tt; t++) {
      // ---- layer 0: acc = b + Wih0*x_t + Whh0*h0[p] ----
      {
        ull accI[BT], accF[BT], accG[BT], accO[BT];
        const float4 wxi = *reinterpret_cast<const float4*>(eWih0 + (size_t)j*4);
        const float4 wxf = *reinterpret_cast<const float4*>(eWih0 + (size_t)(256 + j)*4);
        const float4 wxg = *reinterpret_cast<const float4*>(eWih0 + (size_t)(512 + j)*4);
        const float4 wxo = *reinterpret_cast<const float4*>(eWih0 + (size_t)(768 + j)*4);
        #pragma unroll
        for (int b = 0; b < BT; b++) {
          const float4 xv = *reinterpret_cast<const float4*>(s->xs + b*Tt*4 + t*4);
          accI[b] = f2z(bi0 + wxi.x*xv.x + wxi.y*xv.y + wxi.z*xv.z + wxi.w*xv.w);
          accF[b] = f2z(bf0 + wxf.x*xv.x + wxf.y*xv.y + wxf.z*xv.z + wxf.w*xv.w);
          accG[b] = f2z(bg0 + wxg.x*xv.x + wxg.y*xv.y + wxg.z*xv.z + wxg.w*xv.w);
          accO[b] = f2z(bo0 + wxo.x*xv.x + wxo.y*xv.y + wxo.z*xv.z + wxo.w*xv.w);
        }
        matvec4(eWhh0, j, s->h0[p], accI, accF, accG, accO);
        cell_epilogue(accI, accF, accG, accO, s->c0, s->h0[1 - p], j);
      }
      __syncthreads();   // h0[1-p] ready for everyone
      // ---- layer 1: acc = b + Wih1*h0[1-p] + Whh1*h1[p] ----
      {
        ull accI[BT], accF[BT], accG[BT], accO[BT];
        #pragma unroll
        for (int b = 0; b < BT; b++) {
          accI[b] = f2z(bi1); accF[b] = f2z(bf1);
          accG[b] = f2z(bg1); accO[b] = f2z(bo1);
        }
        matvec4(eWih1, j, s->h0[1 - p], accI, accF, accG, accO);
        matvec4(eWhh1, j, s->h1[p],     accI, accF, accG, accO);
        cell_epilogue(accI, accF, accG, accO, s->c1, s->h1[1 - p], j);
      }
      __syncthreads();
      p ^= 1;
    }

    // ---- snapshot encoder-final states (p == 0 after 50 toggles, but be general) ----
    for (int idx = tid; idx < BT*Hh; idx += NTH) {
      s->eh0[idx] = s->h0[p][idx]; s->ec0[idx] = s->c0[idx];
      s->eh1[idx] = s->h1[p][idx]; s->ec1[idx] = s->c1[idx];
    }
  }
  __syncthreads();

  // ---- confidence head: logits = eh1 @ conf_W.T + conf_b, softmax over K ----
  {
    int warp = tid >> 5, lane = tid & 31;
    for (int task = warp; task < BT*Kk; task += NWARP) {
      int b = task / Kk, k = task - b*Kk;
      float psum = 0.f;
      for (int u = lane; u < Hh; u += 32)
        psum += s->eh1[b*Hh + u] * confW[k*Hh + u];
      #pragma unroll
      for (int off = 16; off; off >>= 1)
        psum += __shfl_down_sync(0xffffffffu, psum, off);
      if (lane == 0) s->logit[b*Kk + k] = psum + confB[k];
    }
  }
  __syncthreads();
  if (tid < BT) {
    int r = row0 + tid;
    float l0 = s->logit[tid*Kk + 0];
    float l1 = s->logit[tid*Kk + 1];
    float l2 = s->logit[tid*Kk + 2];
    float m = fmaxf(l0, fmaxf(l1, l2));
    float e0 = __expf(l0 - m), e1 = __expf(l1 - m), e2 = __expf(l2 - m);
    float inv = 1.f / (e0 + e1 + e2);
    if (r < Bb) {
      float* cp = out + (size_t)Bb*Kk*FSn*2 + (size_t)r*Kk;
      cp[0] = e0*inv; cp[1] = e1*inv; cp[2] = e2*inv;
    }
  }

  // ================= DECODER: K modes × FS steps =================
  for (int km = 0; km < Kk; km++) {
    __syncthreads();
    // restore encoder-final states into parity-0 buffers; init feedback input
    for (int idx = tid; idx < BT*Hh; idx += NTH) {
      s->h0[0][idx] = s->eh0[idx]; s->c0[idx] = s->ec0[idx];
      s->h1[0][idx] = s->eh1[idx]; s->c1[idx] = s->ec1[idx];
    }
    if (tid < BT*2) {
      int b = tid >> 1, d = tid & 1;
      s->inp[tid] = s->xs[b*Tt*4 + (Tt-1)*4 + d];
    }
    __syncthreads();

    const float* dW0 = dWhh0 + (size_t)km*Gg*Hh;
    const float* dW1i = dWih1 + (size_t)km*Gg*Hh;
    const float* dW1h = dWhh1 + (size_t)km*Gg*Hh;

    const float dbi0 = dbih0[km*Gg + j]       + dbhh0[km*Gg + j];
    const float dbf0 = dbih0[km*Gg + 256 + j] + dbhh0[km*Gg + 256 + j];
    const float dbg0 = dbih0[km*Gg + 512 + j] + dbhh0[km*Gg + 512 + j];
    const float dbo0 = dbih0[km*Gg + 768 + j] + dbhh0[km*Gg + 768 + j];
    const float dbi1 = dbih1[km*Gg + j]       + dbhh1[km*Gg + j];
    const float dbf1 = dbih1[km*Gg + 256 + j] + dbhh1[km*Gg + 256 + j];
    const float dbg1 = dbih1[km*Gg + 512 + j] + dbhh1[km*Gg + 512 + j];
    const float dbo1 = dbih1[km*Gg + 768 + j] + dbhh1[km*Gg + 768 + j];
    const float2 wdi = *reinterpret_cast<const float2*>(dWih0 + (size_t)(km*Gg + j)*2);
    const float2 wdf = *reinterpret_cast<const float2*>(dWih0 + (size_t)(km*Gg + 256 + j)*2);
    const float2 wdg = *reinterpret_cast<const float2*>(dWih0 + (size_t)(km*Gg + 512 + j)*2);
    const float2 wdo = *reinterpret_cast<const float2*>(dWih0 + (size_t)(km*Gg + 768 + j)*2);

    int p = 0;
    for (int t = 0; t < FSn; t++) {
      // ---- layer 0 ----
      {
        ull accI[BT], accF[BT], accG[BT], accO[BT];
        #pragma unroll
        for (int b = 0; b < BT; b++) {
          float i0 = s->inp[b*2 + 0], i1 = s->inp[b*2 + 1];
          accI[b] = f2z(dbi0 + wdi.x*i0 + wdi.y*i1);
          accF[b] = f2z(dbf0 + wdf.x*i0 + wdf.y*i1);
          accG[b] = f2z(dbg0 + wdg.x*i0 + wdg.y*i1);
          accO[b] = f2z(dbo0 + wdo.x*i0 + wdo.y*i1);
        }
        matvec4(dW0, j, s->h0[p], accI, accF, accG, accO);
        cell_epilogue(accI, accF, accG, accO, s->c0, s->h0[1 - p], j);
      }
      __syncthreads();
      // ---- layer 1 ----
      {
        ull accI[BT], accF[BT], accG[BT], accO[BT];
        #pragma unroll
        for (int b = 0; b < BT; b++) {
          accI[b] = f2z(dbi1); accF[b] = f2z(dbf1);
          accG[b] = f2z(dbg1); accO[b] = f2z(dbo1);
        }
        matvec4(dW1i, j, s->h0[1 - p], accI, accF, accG, accO);
        matvec4(dW1h, j, s->h1[p],     accI, accF, accG, accO);
        cell_epilogue(accI, accF, accG, accO, s->c1, s->h1[1 - p], j);
      }
      __syncthreads();
      // ---- head: pred[b][d] = h1_new[b] . head_W[km][d] + head_b; feed back + emit ----
      {
        int warp = tid >> 5, lane = tid & 31;
        const float* h1n = s->h1[1 - p];
        for (int task = warp; task < BT*2; task += NWARP) {
          int b = task >> 1, d = task & 1;
          float psum = 0.f;
          const float* hw = headW + (size_t)(km*2 + d)*Hh;
          for (int u = lane; u < Hh; u += 32)
            psum += h1n[b*Hh + u] * hw[u];
          #pragma unroll
          for (int off = 16; off; off >>= 1)
            psum += __shfl_down_sync(0xffffffffu, psum, off);
          if (lane == 0) {
            psum += headB[km*2 + d];
            s->inp[b*2 + d] = psum;
            int r = row0 + b;
            if (r < Bb)
              out[((((size_t)r*Kk + km)*FSn + t)*2) + d] = psum;
          }
        }
      }
      __syncthreads();
      p ^= 1;
    }
  }
}

extern "C" void kernel_launch(void* const* d_in, const int* in_sizes, int n_in,
                              void* d_out, int out_size) {
  (void)in_sizes; (void)n_in; (void)out_size;
  const float* x     = (const float*)d_in[0];
  const float* eWih0 = (const float*)d_in[1];
  const float* eWhh0 = (const float*)d_in[2];
  const float* ebih0 = (const float*)d_in[3];
  const float* ebhh0 = (const float*)d_in[4];
  const float* eWih1 = (const float*)d_in[5];
  const float* eWhh1 = (const float*)d_in[6];
  const float* ebih1 = (const float*)d_in[7];
  const float* ebhh1 = (const float*)d_in[8];
  const float* dWih0 = (const float*)d_in[9];
  const float* dWhh0 = (const float*)d_in[10];
  const float* dbih0 = (const float*)d_in[11];
  const float* dbhh0 = (const float*)d_in[12];
  const float* dWih1 = (const float*)d_in[13];
  const float* dWhh1 = (const float*)d_in[14];
  const float* dbih1 = (const float*)d_in[15];
  const float* dbhh1 = (const float*)d_in[16];
  const float* headW = (const float*)d_in[17];
  const float* headB = (const float*)d_in[18];
  const float* confW = (const float*)d_in[19];
  const float* confB = (const float*)d_in[20];
  float* out = (float*)d_out;

  const int smem_bytes = (int)sizeof(Smem);
  cudaFuncSetAttribute(mml_kernel, cudaFuncAttributeMaxDynamicSharedMemorySize,
                       smem_bytes);

  mml_kernel<<<NBLK, NTH, smem_bytes>>>(
      x, eWih0, eWhh0, ebih0, ebhh0, eWih1, eWhh1, ebih1, ebhh1,
      dWih0, dWhh0, dbih0, dbhh0, dWih1, dWhh1, dbih1, dbhh1,
      headW, headB, confW, confB, out);
}

// round 12
// speedup vs baseline: 13.3823x; 8.4929x over previous
#include <cuda_runtime.h>
#include <cuda_fp16.h>

// Problem constants
#define Hh   256
#define Gg   1024
#define Tt   50
#define Kk   3
#define FSn  6
#define Bb   4096
#define BT   32            // batch rows per CTA (exact: 4096 = 32*128)
#define NTH  512
#define NWARP 16
#define NBLK (Bb/BT)       // 128 CTAs = one wave

#define KC0  17            // layer0 K = 272 = h(256) | x(4) | pad
#define KC1  32            // layer1 K = 512 = h0 | h1
#define A0S  280           // padded row stride (halves) -> conflict-free ldmatrix
#define A1S  520
#define CS   260           // c-state row stride (floats)

// packed weight sizes (uint4 units): [kc][ntp(64)][lane(32)] * 16B
#define W0SZ (KC0*64*32)   // 34816
#define W1SZ (KC1*64*32)   // 65536

__device__ uint4  g_w0e[W0SZ];
__device__ uint4  g_w1e[W1SZ];
__device__ uint4  g_w0d[3*W0SZ];
__device__ uint4  g_w1d[3*W1SZ];
__device__ float2 g_bias2[8*512];   // 8 segments x 1024 floats, gate-packed col order

struct Smem {
  __half A0[BT*A0S];     // layer0 input rows: [h0(256) | x/inp(4) | pad]
  __half A1[BT*A1S];     // layer1 input rows: [h0_new(256) | h1(256) | pad]
  __half eA1[BT*A1S];    // encoder-final snapshot of A1
  float  c0[BT*CS];
  float  c1[BT*CS];
  float  ec0[BT*CS];
  float  ec1[BT*CS];
  float  inp[BT*2];
  float  logit[BT*Kk];
};

static __device__ __forceinline__ float sigm(float v) {
  return 1.0f / (1.0f + __expf(-v));
}
static __device__ __forceinline__ float tanhx(float v) {
  v = fminf(15.0f, fmaxf(-15.0f, v));
  float e = __expf(2.0f * v);
  return (e - 1.0f) / (e + 1.0f);
}

// ===================== converter: fp32 weights -> f16 B-fragment layout =====================
// Packed element (u32 = 2 f16) index: ((kc*64 + ntp)*32 + lane)*4 + q
//   nt = 2*ntp + (q>>1); n_col = nt*8 + (lane>>2)  (gate-packed: n = unit*4 + gate)
//   j_orig = (n_col&3)*256 + (n_col>>2);  k0 = kc*16 + (lane&3)*2 + (q&1)*8; elems k0, k0+1
__global__ void conv_kernel(
    const float* __restrict__ eWih0, const float* __restrict__ eWhh0,
    const float* __restrict__ ebih0, const float* __restrict__ ebhh0,
    const float* __restrict__ eWih1, const float* __restrict__ eWhh1,
    const float* __restrict__ ebih1, const float* __restrict__ ebhh1,
    const float* __restrict__ dWih0, const float* __restrict__ dWhh0,
    const float* __restrict__ dbih0, const float* __restrict__ dbhh0,
    const float* __restrict__ dWih1, const float* __restrict__ dWhh1,
    const float* __restrict__ dbih1, const float* __restrict__ dbhh1)
{
  const int WU0 = W0SZ*4;          // u32 per layer0 matrix
  const int WU1 = W1SZ*4;
  const int WTOT = WU0 + WU1 + 3*WU0 + 3*WU1;   // 1,605,632
  int idx = blockIdx.x * 256 + threadIdx.x;
  if (idx < WTOT) {
    unsigned* dst; int kind; int mode = 0; int local = idx;
    if (local < WU0) { dst = (unsigned*)g_w0e; kind = 0; }
    else if ((local -= WU0) < WU1) { dst = (unsigned*)g_w1e; kind = 1; }
    else if ((local -= WU1) < 3*WU0) {
      mode = local / WU0; local -= mode*WU0;
      dst = (unsigned*)g_w0d + (size_t)mode*WU0; kind = 2;
    } else {
      local -= 3*WU0; mode = local / WU1; local -= mode*WU1;
      dst = (unsigned*)g_w1d + (size_t)mode*WU1; kind = 3;
    }
    int q = local & 3, lane = (local>>2)&31, ntp = (local>>7)&63, kc = local>>13;
    int nt = 2*ntp + (q>>1);
    int ncol = nt*8 + (lane>>2);
    int j = (ncol&3)*256 + (ncol>>2);
    int k0 = kc*16 + (lane&3)*2 + (q&1)*8;     // even
    float v0, v1;
    if (kind == 0) {
      v0 = (k0   < 256) ? eWhh0[j*256 + k0]   : ((k0   < 260) ? eWih0[j*4 + k0-256]   : 0.f);
      v1 = (k0+1 < 256) ? eWhh0[j*256 + k0+1] : ((k0+1 < 260) ? eWih0[j*4 + k0+1-256] : 0.f);
    } else if (kind == 1) {
      v0 = (k0   < 256) ? eWih1[j*256 + k0]   : eWhh1[j*256 + k0-256];
      v1 = (k0+1 < 256) ? eWih1[j*256 + k0+1] : eWhh1[j*256 + k0+1-256];
    } else if (kind == 2) {
      int base = mode*1024 + j;
      v0 = (k0   < 256) ? dWhh0[base*256 + k0]   : ((k0   < 258) ? dWih0[base*2 + k0-256]   : 0.f);
      v1 = (k0+1 < 256) ? dWhh0[base*256 + k0+1] : ((k0+1 < 258) ? dWih0[base*2 + k0+1-256] : 0.f);
    } else {
      int base = mode*1024 + j;
      v0 = (k0   < 256) ? dWih1[base*256 + k0]   : dWhh1[base*256 + k0-256];
      v1 = (k0+1 < 256) ? dWih1[base*256 + k0+1] : dWhh1[base*256 + k0+1-256];
    }
    __half2 h = __floats2half2_rn(v0, v1);
    dst[local] = *(unsigned*)&h;
  } else if (idx < WTOT + 8192) {
    int n = idx - WTOT;
    int seg = n >> 10, col = n & 1023;
    int j = (col&3)*256 + (col>>2);
    float v;
    if      (seg == 0) v = ebih0[j] + ebhh0[j];
    else if (seg == 1) v = ebih1[j] + ebhh1[j];
    else if (seg < 5)  { int m = seg-2; v = dbih0[m*1024+j] + dbhh0[m*1024+j]; }
    else               { int m = seg-5; v = dbih1[m*1024+j] + dbhh1[m*1024+j]; }
    ((float*)g_bias2)[seg*1024 + col] = v;
  }
}

// ===================== MMA primitives =====================
static __device__ __forceinline__ void ldsm4(unsigned* a, unsigned addr) {
  asm volatile("ldmatrix.sync.aligned.m8n8.x4.shared.b16 {%0,%1,%2,%3}, [%4];"
               : "=r"(a[0]),"=r"(a[1]),"=r"(a[2]),"=r"(a[3]) : "r"(addr));
}
static __device__ __forceinline__ void mma16816(float* c, const unsigned* a,
                                                unsigned b0, unsigned b1) {
  asm volatile("mma.sync.aligned.m16n8k16.row.col.f32.f16.f16.f32 "
               "{%0,%1,%2,%3},{%4,%5,%6,%7},{%8,%9},{%0,%1,%2,%3};"
               : "+f"(c[0]),"+f"(c[1]),"+f"(c[2]),"+f"(c[3])
               : "r"(a[0]),"r"(a[1]),"r"(a[2]),"r"(a[3]),"r"(b0),"r"(b1));
}

// Warp w owns n-cols [w*64, w*64+64) = units [w*16, w*16+16), all 32 batch rows.
// C[nt(8)][mh(2)][4]  (64 f32 regs).
template<int KC>
static __device__ __forceinline__ void mma_block(
    const __half* A, int As, const uint4* __restrict__ Wp,
    const float2* __restrict__ bias2, int w, int lane, float C[8][2][4])
{
  #pragma unroll
  for (int nt = 0; nt < 8; nt++) {
    int n0 = (w*8 + nt)*8 + (lane&3)*2;
    float2 bv = bias2[n0>>1];
    #pragma unroll
    for (int mh = 0; mh < 2; mh++) {
      C[nt][mh][0] = bv.x; C[nt][mh][1] = bv.y;
      C[nt][mh][2] = bv.x; C[nt][mh][3] = bv.y;
    }
  }
  int m = lane>>3, r = lane&7;
  unsigned abase = (unsigned)__cvta_generic_to_shared(A);
  unsigned aAddr0 = abase + (unsigned)((((m&1)*8 + r)*As + (m>>1)*8)*2);
  unsigned aAddr1 = aAddr0 + (unsigned)(16*As*2);
  const uint4* p = Wp + (size_t)(w*4)*32 + lane;
  uint4 buf[4];
  #pragma unroll
  for (int i = 0; i < 4; i++) buf[i] = p[i*32];
  #pragma unroll 1
  for (int kc = 0; kc < KC; kc++) {
    unsigned a0[4], a1[4];
    ldsm4(a0, aAddr0); ldsm4(a1, aAddr1);
    aAddr0 += 32; aAddr1 += 32;
    const uint4* pn = p + (size_t)((kc+1 < KC) ? (kc+1) : 0) * 2048;
    #pragma unroll
    for (int ntp = 0; ntp < 4; ntp++) {
      uint4 bw = buf[ntp];
      buf[ntp] = pn[ntp*32];            // prefetch next chunk (overlaps mma)
      mma16816(C[2*ntp  ][0], a0, bw.x, bw.y);
      mma16816(C[2*ntp  ][1], a1, bw.x, bw.y);
      mma16816(C[2*ntp+1][0], a0, bw.z, bw.w);
      mma16816(C[2*ntp+1][1], a1, bw.z, bw.w);
    }
  }
}

// In-register cell update. Gate-packed cols: lanes (l, l^1) jointly hold i,f / g,o
// of the same unit. Even lane computes row r_lo, odd lane row r_hi.
static __device__ __forceinline__ void cell_epi(
    float C[8][2][4], int w, int lane, float* __restrict__ cS,
    __half* __restrict__ d1, int d1s, int off1, __half* __restrict__ d2)
{
  const bool even = (lane & 1) == 0;
  const int rbase = (lane>>2) + (even ? 0 : 8);
  const int uoff = (lane&3) >> 1;
  #pragma unroll
  for (int nt = 0; nt < 8; nt++) {
    int u = (w*8 + nt)*2 + uoff;
    #pragma unroll
    for (int mh = 0; mh < 2; mh++) {
      float x0 = __shfl_xor_sync(0xffffffffu, C[nt][mh][0], 1);
      float x1 = __shfl_xor_sync(0xffffffffu, C[nt][mh][1], 1);
      float x2 = __shfl_xor_sync(0xffffffffu, C[nt][mh][2], 1);
      float x3 = __shfl_xor_sync(0xffffffffu, C[nt][mh][3], 1);
      float gi, gf, gg, go;
      if (even) { gi = C[nt][mh][0]; gf = C[nt][mh][1]; gg = x0; go = x1; }
      else      { gi = x2; gf = x3; gg = C[nt][mh][2]; go = C[nt][mh][3]; }
      int row = mh*16 + rbase;
      float i_ = sigm(gi), f_ = sigm(gf), g_ = tanhx(gg), o_ = sigm(go);
      float cold = cS[row*CS + u];
      float cn = f_*cold + i_*g_;
      cS[row*CS + u] = cn;
      __half hv = __float2half(o_ * tanhx(cn));
      d1[row*d1s + off1 + u] = hv;
      if (d2) d2[row*A1S + u] = hv;
    }
  }
}

// ===================== main kernel =====================
__global__ void __launch_bounds__(NTH, 1)
mml_kernel(const float* __restrict__ x,
           const float* __restrict__ headW, const float* __restrict__ headB,
           const float* __restrict__ confW, const float* __restrict__ confB,
           float* __restrict__ out)
{
  extern __shared__ char raw[];
  Smem* s = reinterpret_cast<Smem*>(raw);
  const int tid = threadIdx.x, w = tid >> 5, lane = tid & 31;
  const int row0 = blockIdx.x * BT;

  // ---- zero-init A0 (incl pad), A1, c0, c1 ----
  {
    unsigned* a0u = (unsigned*)s->A0;
    unsigned* a1u = (unsigned*)s->A1;
    for (int i = tid; i < BT*A0S/2; i += NTH) a0u[i] = 0u;
    for (int i = tid; i < BT*A1S/2; i += NTH) a1u[i] = 0u;
    for (int i = tid; i < BT*CS; i += NTH) { s->c0[i] = 0.f; s->c1[i] = 0.f; }
  }
  __syncthreads();

  // ================= ENCODER =================
  for (int t = 0; t < Tt; t++) {
    if (tid < 128) {   // stage x_t -> A0 cols 256..259
      int b = tid >> 2, d = tid & 3;
      s->A0[b*A0S + 256 + d] = __float2half(x[(row0 + b)*(Tt*4) + t*4 + d]);
    }
    __syncthreads();
    {
      float C[8][2][4];
      mma_block<KC0>(s->A0, A0S, g_w0e, g_bias2 + 0*512, w, lane, C);
      __syncthreads();
      cell_epi(C, w, lane, s->c0, s->A0, A0S, 0, s->A1);
    }
    __syncthreads();
    {
      float C[8][2][4];
      mma_block<KC1>(s->A1, A1S, g_w1e, g_bias2 + 1*512, w, lane, C);
      __syncthreads();
      cell_epi(C, w, lane, s->c1, s->A1, A1S, 256, (__half*)nullptr);
    }
    __syncthreads();
  }

  // ---- snapshot encoder-final state ----
  {
    unsigned* a1u = (unsigned*)s->A1;
    unsigned* eu  = (unsigned*)s->eA1;
    for (int i = tid; i < BT*A1S/2; i += NTH) eu[i] = a1u[i];
    for (int i = tid; i < BT*CS; i += NTH) { s->ec0[i] = s->c0[i]; s->ec1[i] = s->c1[i]; }
  }
  __syncthreads();

  // ---- confidence head ----
  for (int task = w; task < BT*Kk; task += NWARP) {
    int b = task / Kk, k = task - b*Kk;
    float p = 0.f;
    for (int u = lane; u < Hh; u += 32)
      p += __half2float(s->eA1[b*A1S + 256 + u]) * confW[k*Hh + u];
    #pragma unroll
    for (int off = 16; off; off >>= 1) p += __shfl_down_sync(0xffffffffu, p, off);
    if (lane == 0) s->logit[b*Kk + k] = p + confB[k];
  }
  __syncthreads();
  if (tid < BT) {
    int r = row0 + tid;
    float l0 = s->logit[tid*Kk], l1 = s->logit[tid*Kk+1], l2 = s->logit[tid*Kk+2];
    float m = fmaxf(l0, fmaxf(l1, l2));
    float e0 = __expf(l0-m), e1 = __expf(l1-m), e2 = __expf(l2-m);
    float inv = 1.f / (e0 + e1 + e2);
    float* cp = out + (size_t)Bb*Kk*FSn*2 + (size_t)r*Kk;
    cp[0] = e0*inv; cp[1] = e1*inv; cp[2] = e2*inv;
  }

  // ================= DECODER =================
  for (int km = 0; km < Kk; km++) {
    __syncthreads();
    {  // restore encoder-final state
      unsigned* a1u = (unsigned*)s->A1;
      unsigned* eu  = (unsigned*)s->eA1;
      for (int i = tid; i < BT*A1S/2; i += NTH) a1u[i] = eu[i];
      // A0 cols 0..255 <- h0_final (eA1 lower half), as u32 pairs
      unsigned* a0u = (unsigned*)s->A0;
      for (int i = tid; i < BT*128; i += NTH) {
        int b = i >> 7, c = i & 127;
        a0u[b*(A0S/2) + c] = eu[b*(A1S/2) + c];
      }
      for (int i = tid; i < BT*CS; i += NTH) { s->c0[i] = s->ec0[i]; s->c1[i] = s->ec1[i]; }
      if (tid < BT*2) {
        int b = tid >> 1, d = tid & 1;
        s->inp[tid] = x[(row0 + b)*(Tt*4) + (Tt-1)*4 + d];
      }
    }
    __syncthreads();

    const uint4* w0p = g_w0d + (size_t)km*W0SZ;
    const uint4* w1p = g_w1d + (size_t)km*W1SZ;
    const float2* b0p = g_bias2 + (2+km)*512;
    const float2* b1p = g_bias2 + (5+km)*512;

    for (int t = 0; t < FSn; t++) {
      if (tid < 64) {  // stage feedback input -> A0 cols 256,257 (258,259 hit zero W)
        int b = tid >> 1, d = tid & 1;
        s->A0[b*A0S + 256 + d] = __float2half(s->inp[b*2 + d]);
      }
      __syncthreads();
      {
        float C[8][2][4];
        mma_block<KC0>(s->A0, A0S, w0p, b0p, w, lane, C);
        __syncthreads();
        cell_epi(C, w, lane, s->c0, s->A0, A0S, 0, s->A1);
      }
      __syncthreads();
      {
        float C[8][2][4];
        mma_block<KC1>(s->A1, A1S, w1p, b1p, w, lane, C);
        __syncthreads();
        cell_epi(C, w, lane, s->c1, s->A1, A1S, 256, (__half*)nullptr);
      }
      __syncthreads();
      // head
      for (int task = w; task < BT*2; task += NWARP) {
        int b = task >> 1, d = task & 1;
        float p = 0.f;
        const float* hw = headW + (size_t)(km*2 + d)*Hh;
        for (int u = lane; u < Hh; u += 32)
          p += __half2float(s->A1[b*A1S + 256 + u]) * hw[u];
        #pragma unroll
        for (int off = 16; off; off >>= 1) p += __shfl_down_sync(0xffffffffu, p, off);
        if (lane == 0) {
          p += headB[km*2 + d];
          s->inp[b*2 + d] = p;
          int r = row0 + b;
          out[((((size_t)r*Kk + km)*FSn + t)*2) + d] = p;
        }
      }
      __syncthreads();
    }
  }
}

extern "C" void kernel_launch(void* const* d_in, const int* in_sizes, int n_in,
                              void* d_out, int out_size) {
  (void)in_sizes; (void)n_in; (void)out_size;
  const float* x     = (const float*)d_in[0];
  const float* eWih0 = (const float*)d_in[1];
  const float* eWhh0 = (const float*)d_in[2];
  const float* ebih0 = (const float*)d_in[3];
  const float* ebhh0 = (const float*)d_in[4];
  const float* eWih1 = (const float*)d_in[5];
  const float* eWhh1 = (const float*)d_in[6];
  const float* ebih1 = (const float*)d_in[7];
  const float* ebhh1 = (const float*)d_in[8];
  const float* dWih0 = (const float*)d_in[9];
  const float* dWhh0 = (const float*)d_in[10];
  const float* dbih0 = (const float*)d_in[11];
  const float* dbhh0 = (const float*)d_in[12];
  const float* dWih1 = (const float*)d_in[13];
  const float* dWhh1 = (const float*)d_in[14];
  const float* dbih1 = (const float*)d_in[15];
  const float* dbhh1 = (const float*)d_in[16];
  const float* headW = (const float*)d_in[17];
  const float* headB = (const float*)d_in[18];
  const float* confW = (const float*)d_in[19];
  const float* confB = (const float*)d_in[20];
  float* out = (float*)d_out;

  // 1) pack weights/biases into fragment layout (f16)
  const int WU0 = W0SZ*4, WU1 = W1SZ*4;
  const int total = WU0 + WU1 + 3*WU0 + 3*WU1 + 8192;
  conv_kernel<<<(total + 255)/256, 256>>>(
      eWih0, eWhh0, ebih0, ebhh0, eWih1, eWhh1, ebih1, ebhh1,
      dWih0, dWhh0, dbih0, dbhh0, dWih1, dWhh1, dbih1, dbhh1);

  // 2) persistent LSTM kernel
  const int smem_bytes = (int)sizeof(Smem);
  cudaFuncSetAttribute(mml_kernel, cudaFuncAttributeMaxDynamicSharedMemorySize,
                       smem_bytes);
  mml_kernel<<<NBLK, NTH, smem_bytes>>>(x, headW, headB, confW, confB, out);
}